// round 1
// baseline (speedup 1.0000x reference)
#include <cuda_runtime.h>

#define BB   256
#define TT   32
#define CNN  512
#define HWSQ 196      // 14*14
#define HID  8
#define NG   32       // 4*HID gates
#define VV   37

// scratch for x0 = fc_in(pooled)  [B, V]
__device__ float g_x0[BB * VV];

// ---------------------------------------------------------------------------
// Kernel A: fused AdaptiveAvgPool2d(1) + fc_in.
// grid = B, block = 256 (8 warps). Coalesced: each warp reduces one channel
// (49 float4 contiguous) via shfl; then warp-per-output fc_in dot over 512.
// ---------------------------------------------------------------------------
__global__ __launch_bounds__(256) void pool_fc_kernel(
    const float* __restrict__ feat,   // [B, 512, 14, 14]
    const float* __restrict__ W_in,   // [37, 512]
    const float* __restrict__ b_in)   // [37]
{
    __shared__ float pooled[CNN];
    const int b    = blockIdx.x;
    const int warp = threadIdx.x >> 5;
    const int lane = threadIdx.x & 31;

    const float4* base = reinterpret_cast<const float4*>(feat + (size_t)b * CNN * HWSQ);

    // each channel = 196 floats = 49 float4 (contiguous)
    for (int c = warp; c < CNN; c += 8) {
        const float4* p = base + c * 49;
        float4 a = p[lane];                       // lanes 0..31 -> float4 0..31
        float s = a.x + a.y + a.z + a.w;
        if (lane < 17) {                          // float4 32..48
            float4 q = p[lane + 32];
            s += q.x + q.y + q.z + q.w;
        }
        #pragma unroll
        for (int o = 16; o > 0; o >>= 1)
            s += __shfl_down_sync(0xffffffffu, s, o);
        if (lane == 0) pooled[c] = s * (1.0f / 196.0f);
    }
    __syncthreads();

    // fc_in: 37 outputs, one warp per output (round-robin)
    for (int v = warp; v < VV; v += 8) {
        const float* w = W_in + v * CNN;
        float s = 0.0f;
        #pragma unroll 4
        for (int k = lane; k < CNN; k += 32)
            s += pooled[k] * w[k];
        #pragma unroll
        for (int o = 16; o > 0; o >>= 1)
            s += __shfl_down_sync(0xffffffffu, s, o);
        if (lane == 0) g_x0[b * VV + v] = s + b_in[v];
    }
}

// ---------------------------------------------------------------------------
// Kernel B: one warp per batch element. 32 LSTM steps (teacher forcing),
// fc_out, then softmax over the TIME axis. Gate g lives on lane g; hidden
// state h[j]/c[j] live on lanes j<8; h broadcast via shfl.
// ---------------------------------------------------------------------------
__global__ __launch_bounds__(32) void lstm_kernel(
    const float* __restrict__ captions, // [B, T, V]
    const float* __restrict__ W_ih,     // [32, 37]
    const float* __restrict__ b_ih,     // [32]
    const float* __restrict__ W_hh,     // [32, 8]
    const float* __restrict__ b_hh,     // [32]
    const float* __restrict__ W_out,    // [37, 8]
    const float* __restrict__ b_out,    // [37]
    float* __restrict__ out)            // [B, T, V]
{
    __shared__ float sWih[NG * VV];     // [32][37] stride 37 (coprime w/ 32)
    __shared__ float sWhh[NG * 9];      // [32][8] padded to 9 (conflict-free)
    __shared__ float sWout[VV * 9];     // [37][8] padded to 9
    __shared__ float sb[NG];            // b_ih + b_hh
    __shared__ float sbo[VV];
    __shared__ float xb[VV + 3];
    __shared__ float logits[TT * VV];   // [32][37]

    const int b    = blockIdx.x;
    const int lane = threadIdx.x;       // blockDim == 32

    // stage weights into shared
    for (int i = lane; i < NG * VV; i += 32) sWih[i] = W_ih[i];
    for (int i = lane; i < NG * HID; i += 32) {
        int g = i >> 3, j = i & 7;
        sWhh[g * 9 + j] = W_hh[i];
    }
    for (int i = lane; i < VV * HID; i += 32) {
        int v = i / 8, j = i & 7;
        sWout[v * 9 + j] = W_out[i];
    }
    sb[lane] = b_ih[lane] + b_hh[lane];
    if (lane < VV)      sbo[lane]      = b_out[lane];
    if (lane < VV - 32) sbo[32 + lane] = b_out[32 + lane];
    __syncwarp();

    float h = 0.0f, c = 0.0f;
    const int v1 = lane;            // first owned output column
    const int v2 = 32 + lane;       // second owned column, valid if lane<5

    for (int t = 0; t < TT; ++t) {
        // input vector for this step
        const float* xsrc = (t == 0) ? (g_x0 + b * VV)
                                     : (captions + ((size_t)b * TT + (t - 1)) * VV);
        xb[lane] = xsrc[lane];
        if (lane < VV - 32) xb[32 + lane] = xsrc[32 + lane];
        __syncwarp();

        // gate[lane] = b + x . W_ih[lane,:] + h . W_hh[lane,:]
        float gate = sb[lane];
        const float* wrow = &sWih[lane * VV];
        #pragma unroll
        for (int k = 0; k < VV; ++k)
            gate = fmaf(xb[k], wrow[k], gate);
        #pragma unroll
        for (int j = 0; j < HID; ++j) {
            float hv = __shfl_sync(0xffffffffu, h, j);
            gate = fmaf(hv, sWhh[lane * 9 + j], gate);
        }

        // gather i,f,g,o for hidden unit (lane&7); only lanes<8 use it
        int j8 = lane & 7;
        float gi = __shfl_sync(0xffffffffu, gate, j8);
        float gf = __shfl_sync(0xffffffffu, gate, j8 + 8);
        float gg = __shfl_sync(0xffffffffu, gate, j8 + 16);
        float go = __shfl_sync(0xffffffffu, gate, j8 + 24);
        if (lane < HID) {
            float i_ = 1.0f / (1.0f + __expf(-gi));
            float f_ = 1.0f / (1.0f + __expf(-gf));
            float g_ = tanhf(gg);
            float o_ = 1.0f / (1.0f + __expf(-go));
            c = fmaf(f_, c, i_ * g_);
            h = o_ * tanhf(c);
        }

        // fc_out: out[v] = b_out[v] + h . W_out[v,:]
        float o1 = sbo[v1];
        float o2 = (lane < 5) ? sbo[v2] : 0.0f;
        #pragma unroll
        for (int j = 0; j < HID; ++j) {
            float hv = __shfl_sync(0xffffffffu, h, j);
            o1 = fmaf(hv, sWout[v1 * 9 + j], o1);
            if (lane < 5) o2 = fmaf(hv, sWout[v2 * 9 + j], o2);
        }
        logits[t * VV + v1] = o1;
        if (lane < 5) logits[t * VV + v2] = o2;
        __syncwarp();   // xb rewritten next iteration
    }

    // softmax over TIME axis, per (b, v). Each lane owns column v1 (and v2).
    float m1 = -1e30f, m2 = -1e30f;
    #pragma unroll
    for (int t = 0; t < TT; ++t) {
        m1 = fmaxf(m1, logits[t * VV + v1]);
        if (lane < 5) m2 = fmaxf(m2, logits[t * VV + v2]);
    }
    float s1 = 0.0f, s2 = 0.0f;
    #pragma unroll
    for (int t = 0; t < TT; ++t) {
        float e1 = __expf(logits[t * VV + v1] - m1);
        s1 += e1;
        logits[t * VV + v1] = e1;
        if (lane < 5) {
            float e2 = __expf(logits[t * VV + v2] - m2);
            s2 += e2;
            logits[t * VV + v2] = e2;
        }
    }
    float r1 = 1.0f / s1;
    float r2 = (lane < 5) ? (1.0f / s2) : 0.0f;

    float* ob = out + (size_t)b * TT * VV;
    #pragma unroll
    for (int t = 0; t < TT; ++t) {
        ob[t * VV + v1] = logits[t * VV + v1] * r1;            // coalesced per t
        if (lane < 5) ob[t * VV + v2] = logits[t * VV + v2] * r2;
    }
}

// ---------------------------------------------------------------------------
extern "C" void kernel_launch(void* const* d_in, const int* in_sizes, int n_in,
                              void* d_out, int out_size)
{
    const float* features = (const float*)d_in[0];
    const float* captions = (const float*)d_in[1];
    const float* W_ih     = (const float*)d_in[2];
    const float* b_ih     = (const float*)d_in[3];
    const float* W_hh     = (const float*)d_in[4];
    const float* b_hh     = (const float*)d_in[5];
    const float* W_in     = (const float*)d_in[6];
    const float* b_in     = (const float*)d_in[7];
    const float* W_out    = (const float*)d_in[8];
    const float* b_out    = (const float*)d_in[9];
    // d_in[10] = isTraining (always 1 in this dataset; teacher-forcing path)
    float* out = (float*)d_out;

    pool_fc_kernel<<<BB, 256>>>(features, W_in, b_in);
    lstm_kernel<<<BB, 32>>>(captions, W_ih, b_ih, W_hh, b_hh, W_out, b_out, out);
    (void)in_sizes; (void)n_in; (void)out_size;
}

// round 2
// speedup vs baseline: 2.2014x; 2.2014x over previous
#include <cuda_runtime.h>

#define BB   256
#define TT   32
#define CNN  512
#define HWSQ 196      // 14*14
#define HID  8
#define NG   32       // 4*HID gates
#define VV   37
#define NTHR 512
#define NWARP (NTHR/32)

__device__ __forceinline__ float sigmoidf_(float x) {
    return 1.0f / (1.0f + __expf(-x));
}

// ---------------------------------------------------------------------------
// One fully fused kernel. grid = B (256), block = 512 (16 warps).
// Phase 1: pool 512ch x 196 (coalesced float4, warp-per-channel)
// Phase 2: fc_in  -> x0 (smem)
// Phase 3: xproj[t][gate] = x_t . W_ih^T + b_ih + b_hh  (warp-per-t, parallel)
// Phase 4: warp 0 runs the 32-step recurrence (register-resident h, c)
// Phase 5: fc_out (warp-per-t) + softmax over TIME + coalesced store
// ---------------------------------------------------------------------------
__global__ __launch_bounds__(NTHR) void lstm_fused_kernel(
    const float* __restrict__ feat,     // [B, 512, 14, 14]
    const float* __restrict__ captions, // [B, T, V]
    const float* __restrict__ W_ih,     // [32, 37]
    const float* __restrict__ b_ih,     // [32]
    const float* __restrict__ W_hh,     // [32, 8]
    const float* __restrict__ b_hh,     // [32]
    const float* __restrict__ W_in,     // [37, 512]
    const float* __restrict__ b_in,     // [37]
    const float* __restrict__ W_out,    // [37, 8]
    const float* __restrict__ b_out,    // [37]
    float* __restrict__ out)            // [B, T, V]
{
    __shared__ float pooled[CNN];
    __shared__ float xs[VV];            // x0 = fc_in(pooled)
    __shared__ float sWih[NG * VV];     // stride 37 (5 mod 32 -> conflict-free)
    __shared__ float sb[NG];            // b_ih + b_hh
    __shared__ float xproj[TT * NG];    // [t][gate]
    __shared__ float hbuf[TT * HID];    // h history [t][j]
    __shared__ float logits[TT * VV];   // [t][v]

    const int b    = blockIdx.x;
    const int tid  = threadIdx.x;
    const int warp = tid >> 5;
    const int lane = tid & 31;

    // ---- stage small weights ----
    for (int i = tid; i < NG * VV; i += NTHR) sWih[i] = W_ih[i];
    if (tid < NG) sb[tid] = b_ih[tid] + b_hh[tid];

    // ---- Phase 1: adaptive avg pool (each warp: channels w, w+16, ...) ----
    const float4* base = reinterpret_cast<const float4*>(feat + (size_t)b * CNN * HWSQ);
    for (int c = warp; c < CNN; c += NWARP) {
        const float4* p = base + c * 49;           // 196 floats = 49 float4
        float4 a = p[lane];
        float s = a.x + a.y + a.z + a.w;
        if (lane < 17) {
            float4 q = p[lane + 32];
            s += q.x + q.y + q.z + q.w;
        }
        #pragma unroll
        for (int o = 16; o > 0; o >>= 1)
            s += __shfl_down_sync(0xffffffffu, s, o);
        if (lane == 0) pooled[c] = s * (1.0f / 196.0f);
    }
    __syncthreads();

    // ---- Phase 2: fc_in, warp-per-output ----
    for (int v = warp; v < VV; v += NWARP) {
        const float* w = W_in + v * CNN;
        float s = 0.0f;
        #pragma unroll 4
        for (int k = lane; k < CNN; k += 32)
            s += pooled[k] * w[k];
        #pragma unroll
        for (int o = 16; o > 0; o >>= 1)
            s += __shfl_down_sync(0xffffffffu, s, o);
        if (lane == 0) xs[v] = s + b_in[v];
    }
    __syncthreads();

    // ---- Phase 3: xproj (warp w handles t = w, w+16) ----
    for (int t = warp; t < TT; t += NWARP) {
        const float* x = (t == 0) ? xs : (captions + ((size_t)b * TT + (t - 1)) * VV);
        float acc = sb[lane];
        const float* wrow = &sWih[lane * VV];
        #pragma unroll
        for (int k = 0; k < VV; ++k)
            acc = fmaf(x[k], wrow[k], acc);
        xproj[t * NG + lane] = acc;
    }
    __syncthreads();

    // ---- Phase 4: recurrence (warp 0 only) ----
    if (warp == 0) {
        // W_hh row for this lane's gate (8 floats, coalesced float4 loads)
        const float4* w4 = reinterpret_cast<const float4*>(W_hh);
        float4 wa = w4[lane * 2];
        float4 wb = w4[lane * 2 + 1];
        float whh0 = wa.x, whh1 = wa.y, whh2 = wa.z, whh3 = wa.w;
        float whh4 = wb.x, whh5 = wb.y, whh6 = wb.z, whh7 = wb.w;

        float h0 = 0.f, h1 = 0.f, h2 = 0.f, h3 = 0.f;
        float h4 = 0.f, h5 = 0.f, h6 = 0.f, h7 = 0.f;
        float c = 0.f;                 // lane l holds c of unit (l & 7)
        const int j8 = lane & 7;

        #pragma unroll
        for (int t = 0; t < TT; ++t) {
            // gate = xproj + h . W_hh[row]  (two accumulators to shorten chain)
            float ga = xproj[t * NG + lane];
            float gb = 0.0f;
            ga = fmaf(h0, whh0, ga);  gb = fmaf(h1, whh1, gb);
            ga = fmaf(h2, whh2, ga);  gb = fmaf(h3, whh3, gb);
            ga = fmaf(h4, whh4, ga);  gb = fmaf(h5, whh5, gb);
            ga = fmaf(h6, whh6, ga);  gb = fmaf(h7, whh7, gb);
            float gate = ga + gb;

            // gather i,f,g,o for unit j8 (every lane redundantly computes)
            float gi = __shfl_sync(0xffffffffu, gate, j8);
            float gf = __shfl_sync(0xffffffffu, gate, j8 + 8);
            float gg = __shfl_sync(0xffffffffu, gate, j8 + 16);
            float go = __shfl_sync(0xffffffffu, gate, j8 + 24);

            float i_ = sigmoidf_(gi);
            float f_ = sigmoidf_(gf);
            float g_ = tanhf(gg);
            float o_ = sigmoidf_(go);
            c = fmaf(f_, c, i_ * g_);
            float hn = o_ * tanhf(c);

            // broadcast new h (lanes 0..7 hold units 0..7)
            h0 = __shfl_sync(0xffffffffu, hn, 0);
            h1 = __shfl_sync(0xffffffffu, hn, 1);
            h2 = __shfl_sync(0xffffffffu, hn, 2);
            h3 = __shfl_sync(0xffffffffu, hn, 3);
            h4 = __shfl_sync(0xffffffffu, hn, 4);
            h5 = __shfl_sync(0xffffffffu, hn, 5);
            h6 = __shfl_sync(0xffffffffu, hn, 6);
            h7 = __shfl_sync(0xffffffffu, hn, 7);

            if (lane < HID) hbuf[t * HID + lane] = hn;   // off critical path
        }
    }
    __syncthreads();

    // ---- Phase 5a: fc_out, warp w handles t = w, w+16 ----
    for (int t = warp; t < TT; t += NWARP) {
        float acc1 = b_out[lane];                         // v1 = lane (< 37)
        float acc2 = (lane < VV - 32) ? b_out[32 + lane] : 0.0f;
        #pragma unroll
        for (int j = 0; j < HID; ++j) {
            float hv = hbuf[t * HID + j];                 // broadcast LDS
            acc1 = fmaf(hv, W_out[lane * HID + j], acc1);
            if (lane < VV - 32)
                acc2 = fmaf(hv, W_out[(32 + lane) * HID + j], acc2);
        }
        logits[t * VV + lane] = acc1;
        if (lane < VV - 32) logits[t * VV + 32 + lane] = acc2;
    }
    __syncthreads();

    // ---- Phase 5b: softmax over TIME axis (thread v owns column v) ----
    if (tid < VV) {
        float m = -1e30f;
        #pragma unroll
        for (int t = 0; t < TT; ++t)
            m = fmaxf(m, logits[t * VV + tid]);
        float s = 0.0f;
        #pragma unroll
        for (int t = 0; t < TT; ++t) {
            float e = __expf(logits[t * VV + tid] - m);
            s += e;
            logits[t * VV + tid] = e;
        }
        float r = 1.0f / s;
        #pragma unroll
        for (int t = 0; t < TT; ++t)
            logits[t * VV + tid] *= r;
    }
    __syncthreads();

    // ---- Phase 5c: coalesced store ----
    float* ob = out + (size_t)b * TT * VV;
    for (int i = tid; i < TT * VV; i += NTHR)
        ob[i] = logits[i];
}

// ---------------------------------------------------------------------------
extern "C" void kernel_launch(void* const* d_in, const int* in_sizes, int n_in,
                              void* d_out, int out_size)
{
    const float* features = (const float*)d_in[0];
    const float* captions = (const float*)d_in[1];
    const float* W_ih     = (const float*)d_in[2];
    const float* b_ih     = (const float*)d_in[3];
    const float* W_hh     = (const float*)d_in[4];
    const float* b_hh     = (const float*)d_in[5];
    const float* W_in     = (const float*)d_in[6];
    const float* b_in     = (const float*)d_in[7];
    const float* W_out    = (const float*)d_in[8];
    const float* b_out    = (const float*)d_in[9];
    float* out = (float*)d_out;

    lstm_fused_kernel<<<BB, NTHR>>>(features, captions, W_ih, b_ih, W_hh, b_hh,
                                    W_in, b_in, W_out, b_out, out);
    (void)in_sizes; (void)n_in; (void)out_size;
}

// round 3
// speedup vs baseline: 2.5082x; 1.1393x over previous
#include <cuda_runtime.h>

#define BB   256
#define TT   32
#define CNN  512
#define HWSQ 196      // 14*14
#define HID  8
#define NG   32       // 4*HID gates
#define VV   37
#define NTHR 512
#define NWARP (NTHR/32)
#define CPW  (CNN/NWARP)   // 32 channels per warp
#define UNR  4             // channels reduced per batch of loads

__device__ __forceinline__ float sigmoidf_(float x) {
    return 1.0f / (1.0f + __expf(-x));
}

// ---------------------------------------------------------------------------
// One fully fused kernel. grid = B (256), block = 512 (16 warps).
// Phase 1: pool 512ch x 196 — warp owns 32 contiguous channels, 4-channel
//          unroll => 8 independent LDG.128 in flight before any reduction.
// Phase 2: fc_in  -> x0 (smem)
// Phase 3: xproj[t][gate] = x_t . W_ih^T + b_ih + b_hh  (warp-per-t)
// Phase 4: warp 0 runs the 32-step recurrence (register-resident h, c)
// Phase 5: fc_out (warp-per-t) + softmax over TIME + coalesced store
// ---------------------------------------------------------------------------
__global__ __launch_bounds__(NTHR) void lstm_fused_kernel(
    const float* __restrict__ feat,     // [B, 512, 14, 14]
    const float* __restrict__ captions, // [B, T, V]
    const float* __restrict__ W_ih,     // [32, 37]
    const float* __restrict__ b_ih,     // [32]
    const float* __restrict__ W_hh,     // [32, 8]
    const float* __restrict__ b_hh,     // [32]
    const float* __restrict__ W_in,     // [37, 512]
    const float* __restrict__ b_in,     // [37]
    const float* __restrict__ W_out,    // [37, 8]
    const float* __restrict__ b_out,    // [37]
    float* __restrict__ out)            // [B, T, V]
{
    __shared__ float pooled[CNN];
    __shared__ float xs[VV];            // x0 = fc_in(pooled)
    __shared__ float sWih[NG * VV];     // stride 37 (conflict-free mod 32)
    __shared__ float sb[NG];            // b_ih + b_hh
    __shared__ float xproj[TT * NG];    // [t][gate]
    __shared__ float hbuf[TT * HID];    // h history [t][j]
    __shared__ float logits[TT * VV];   // [t][v]

    const int b    = blockIdx.x;
    const int tid  = threadIdx.x;
    const int warp = tid >> 5;
    const int lane = tid & 31;

    // ---- stage small weights (before the big memory phase) ----
    for (int i = tid; i < NG * VV; i += NTHR) sWih[i] = W_ih[i];
    if (tid < NG) sb[tid] = b_ih[tid] + b_hh[tid];

    // ---- Phase 1: adaptive avg pool, high-MLP version ----
    // warp owns contiguous channels [warp*32, warp*32+32)
    const float4* base = reinterpret_cast<const float4*>(feat + (size_t)b * CNN * HWSQ);
    const int c0 = warp * CPW;
    #pragma unroll
    for (int cc = 0; cc < CPW; cc += UNR) {
        float s[UNR];
        // issue all 2*UNR loads before any arithmetic/shuffles
        float4 a[UNR], q[UNR];
        #pragma unroll
        for (int u = 0; u < UNR; ++u) {
            const float4* p = base + (size_t)(c0 + cc + u) * 49;   // 196 floats
            a[u] = p[lane];
            if (lane < 17) q[u] = p[lane + 32];
        }
        #pragma unroll
        for (int u = 0; u < UNR; ++u) {
            s[u] = a[u].x + a[u].y + a[u].z + a[u].w;
            if (lane < 17) s[u] += q[u].x + q[u].y + q[u].z + q[u].w;
        }
        // 4 independent shuffle-reduction trees (pipeline across u)
        #pragma unroll
        for (int o = 16; o > 0; o >>= 1) {
            #pragma unroll
            for (int u = 0; u < UNR; ++u)
                s[u] += __shfl_down_sync(0xffffffffu, s[u], o);
        }
        if (lane == 0) {
            #pragma unroll
            for (int u = 0; u < UNR; ++u)
                pooled[c0 + cc + u] = s[u] * (1.0f / 196.0f);
        }
    }
    __syncthreads();

    // ---- Phase 2: fc_in, warp-per-output ----
    for (int v = warp; v < VV; v += NWARP) {
        const float* w = W_in + v * CNN;
        float s = 0.0f;
        #pragma unroll 4
        for (int k = lane; k < CNN; k += 32)
            s += pooled[k] * w[k];
        #pragma unroll
        for (int o = 16; o > 0; o >>= 1)
            s += __shfl_down_sync(0xffffffffu, s, o);
        if (lane == 0) xs[v] = s + b_in[v];
    }
    __syncthreads();

    // ---- Phase 3: xproj (warp w handles t = w, w+16) ----
    for (int t = warp; t < TT; t += NWARP) {
        const float* x = (t == 0) ? xs : (captions + ((size_t)b * TT + (t - 1)) * VV);
        float acc = sb[lane];
        const float* wrow = &sWih[lane * VV];
        #pragma unroll
        for (int k = 0; k < VV; ++k)
            acc = fmaf(x[k], wrow[k], acc);
        xproj[t * NG + lane] = acc;
    }
    __syncthreads();

    // ---- Phase 4: recurrence (warp 0 only) ----
    if (warp == 0) {
        const float4* w4 = reinterpret_cast<const float4*>(W_hh);
        float4 wa = w4[lane * 2];
        float4 wb = w4[lane * 2 + 1];
        float whh0 = wa.x, whh1 = wa.y, whh2 = wa.z, whh3 = wa.w;
        float whh4 = wb.x, whh5 = wb.y, whh6 = wb.z, whh7 = wb.w;

        float h0 = 0.f, h1 = 0.f, h2 = 0.f, h3 = 0.f;
        float h4 = 0.f, h5 = 0.f, h6 = 0.f, h7 = 0.f;
        float c = 0.f;
        const int j8 = lane & 7;

        #pragma unroll
        for (int t = 0; t < TT; ++t) {
            float ga = xproj[t * NG + lane];
            float gb = 0.0f;
            ga = fmaf(h0, whh0, ga);  gb = fmaf(h1, whh1, gb);
            ga = fmaf(h2, whh2, ga);  gb = fmaf(h3, whh3, gb);
            ga = fmaf(h4, whh4, ga);  gb = fmaf(h5, whh5, gb);
            ga = fmaf(h6, whh6, ga);  gb = fmaf(h7, whh7, gb);
            float gate = ga + gb;

            float gi = __shfl_sync(0xffffffffu, gate, j8);
            float gf = __shfl_sync(0xffffffffu, gate, j8 + 8);
            float gg = __shfl_sync(0xffffffffu, gate, j8 + 16);
            float go = __shfl_sync(0xffffffffu, gate, j8 + 24);

            float i_ = sigmoidf_(gi);
            float f_ = sigmoidf_(gf);
            float g_ = tanhf(gg);
            float o_ = sigmoidf_(go);
            c = fmaf(f_, c, i_ * g_);
            float hn = o_ * tanhf(c);

            h0 = __shfl_sync(0xffffffffu, hn, 0);
            h1 = __shfl_sync(0xffffffffu, hn, 1);
            h2 = __shfl_sync(0xffffffffu, hn, 2);
            h3 = __shfl_sync(0xffffffffu, hn, 3);
            h4 = __shfl_sync(0xffffffffu, hn, 4);
            h5 = __shfl_sync(0xffffffffu, hn, 5);
            h6 = __shfl_sync(0xffffffffu, hn, 6);
            h7 = __shfl_sync(0xffffffffu, hn, 7);

            if (lane < HID) hbuf[t * HID + lane] = hn;   // off critical path
        }
    }
    __syncthreads();

    // ---- Phase 5a: fc_out, warp w handles t = w, w+16 ----
    for (int t = warp; t < TT; t += NWARP) {
        float acc1 = b_out[lane];
        float acc2 = (lane < VV - 32) ? b_out[32 + lane] : 0.0f;
        #pragma unroll
        for (int j = 0; j < HID; ++j) {
            float hv = hbuf[t * HID + j];
            acc1 = fmaf(hv, W_out[lane * HID + j], acc1);
            if (lane < VV - 32)
                acc2 = fmaf(hv, W_out[(32 + lane) * HID + j], acc2);
        }
        logits[t * VV + lane] = acc1;
        if (lane < VV - 32) logits[t * VV + 32 + lane] = acc2;
    }
    __syncthreads();

    // ---- Phase 5b: softmax over TIME axis (thread v owns column v) ----
    if (tid < VV) {
        float m = -1e30f;
        #pragma unroll
        for (int t = 0; t < TT; ++t)
            m = fmaxf(m, logits[t * VV + tid]);
        float s = 0.0f;
        #pragma unroll
        for (int t = 0; t < TT; ++t) {
            float e = __expf(logits[t * VV + tid] - m);
            s += e;
            logits[t * VV + tid] = e;
        }
        float r = 1.0f / s;
        #pragma unroll
        for (int t = 0; t < TT; ++t)
            logits[t * VV + tid] *= r;
    }
    __syncthreads();

    // ---- Phase 5c: coalesced store ----
    float* ob = out + (size_t)b * TT * VV;
    for (int i = tid; i < TT * VV; i += NTHR)
        ob[i] = logits[i];
}

// ---------------------------------------------------------------------------
extern "C" void kernel_launch(void* const* d_in, const int* in_sizes, int n_in,
                              void* d_out, int out_size)
{
    const float* features = (const float*)d_in[0];
    const float* captions = (const float*)d_in[1];
    const float* W_ih     = (const float*)d_in[2];
    const float* b_ih     = (const float*)d_in[3];
    const float* W_hh     = (const float*)d_in[4];
    const float* b_hh     = (const float*)d_in[5];
    const float* W_in     = (const float*)d_in[6];
    const float* b_in     = (const float*)d_in[7];
    const float* W_out    = (const float*)d_in[8];
    const float* b_out    = (const float*)d_in[9];
    float* out = (float*)d_out;

    lstm_fused_kernel<<<BB, NTHR>>>(features, captions, W_ih, b_ih, W_hh, b_hh,
                                    W_in, b_in, W_out, b_out, out);
    (void)in_sizes; (void)n_in; (void)out_size;
}